// round 4
// baseline (speedup 1.0000x reference)
#include <cuda_runtime.h>
#include <cstdint>
#include <cstddef>

// ---------------------------------------------------------------------------
// GraphSAGE 2-layer (N=100000, E=800000, 128 -> 128 -> 47, fp32):
//   scatter-mean -> GEMM1(+bias,+row L2 norm) -> BN stats -> BN+ReLU
//   -> scatter-mean -> GEMM2(+bias,+row L2 norm) -> out
// edge_index dtype (int32 vs int64) is detected on-device: JAX with x64
// disabled materializes "int64" arrays as int32.
// ---------------------------------------------------------------------------

#define NMAX 100000
#define CH   128
#define KC   32          // K-chunk for GEMMs
#define ASTR 36          // inS row stride (KC + 4 pad)

__device__ __align__(16) float g_agg[(size_t)NMAX * CH];
__device__ __align__(16) float g_h[(size_t)NMAX * CH];
__device__ __align__(16) float g_deg[NMAX];
__device__ __align__(16) float g_wT1[256 * 128];   // [k][c]
__device__ __align__(16) float g_wT2[256 * 48];    // [k][c] (c padded to 48)
__device__ __align__(16) float g_bnsum[128];
__device__ __align__(16) float g_bnsq[128];
__device__ __align__(16) float g_bnscale[128];
__device__ __align__(16) float g_bnshift[128];
__device__ int g_ei32;   // 1 if edge_index is int32, 0 if int64

// ---------------------------------------------------------------------------
// Probe edge_index dtype. int32 data read as int64 fuses two random indices:
// value >= 2^32 unless the high word is 0 (p ~ 1e-5 per sample).
__global__ void detect_ei(const void* ei, int Nn) {
    if (threadIdx.x == 0 && blockIdx.x == 0) {
        const long long* p = (const long long*)ei;
        int is32 = 0;
        for (int i = 0; i < 16; i++) {
            long long v = p[i];
            if (v < 0 || v >= (long long)Nn) { is32 = 1; break; }
        }
        g_ei32 = is32;
    }
}

__global__ void zero_kernel(int nf4, int withAux, int Nn) {
    int i = blockIdx.x * blockDim.x + threadIdx.x;
    int stride = gridDim.x * blockDim.x;
    float4 z = make_float4(0.f, 0.f, 0.f, 0.f);
    float4* a4 = (float4*)g_agg;
    for (int j = i; j < nf4; j += stride) a4[j] = z;
    if (withAux) {
        for (int j = i; j < Nn; j += stride) g_deg[j] = 0.f;
        if (i < 128) { g_bnsum[i] = 0.f; g_bnsq[i] = 0.f; }
    }
}

__global__ void prep_weights(const float* __restrict__ w1l, const float* __restrict__ w1r,
                             const float* __restrict__ w2l, const float* __restrict__ w2r) {
    int t = blockIdx.x * blockDim.x + threadIdx.x;
    if (t < 256 * 128) {
        int k = t >> 7, c = t & 127;
        g_wT1[t] = (k < 128) ? w1l[c * 128 + k] : w1r[c * 128 + (k - 128)];
    }
    if (t < 256 * 48) {
        int k = t / 48, c = t - k * 48;
        float v = 0.f;
        if (c < 47) v = (k < 128) ? w2l[c * 128 + k] : w2r[c * 128 + (k - 128)];
        g_wT2[t] = v;
    }
}

// One warp per edge: lane l covers columns {l, l+32, l+64, l+96}.
// Dense 128B gather loads and dense 128B atomic waves.
__global__ void __launch_bounds__(256) scatter_kernel(
    const float* __restrict__ feat, const void* __restrict__ ei,
    int E, int useH, int withDeg, int Nn)
{
    if (useH) feat = (const float*)g_h;
    const int is32 = g_ei32;
    int gw   = (blockIdx.x * blockDim.x + threadIdx.x) >> 5;
    int lane = threadIdx.x & 31;
    int nw   = (gridDim.x * blockDim.x) >> 5;
    for (int e = gw; e < E; e += nw) {
        int idx = -1;
        if (lane < 2) {
            size_t off = lane ? (size_t)E + e : (size_t)e;
            if (is32) idx = ((const int*)ei)[off];
            else      idx = (int)((const long long*)ei)[off];
        }
        int src = __shfl_sync(0xffffffffu, idx, 0);
        int dst = __shfl_sync(0xffffffffu, idx, 1);
        if ((unsigned)src >= (unsigned)Nn || (unsigned)dst >= (unsigned)Nn) continue;
        const float* sp = feat + (size_t)src * 128 + lane;
        float* dp = g_agg + (size_t)dst * 128 + lane;
        float v0 = sp[0];
        float v1 = sp[32];
        float v2 = sp[64];
        float v3 = sp[96];
        atomicAdd(dp +  0, v0);
        atomicAdd(dp + 32, v1);
        atomicAdd(dp + 64, v2);
        atomicAdd(dp + 96, v3);
        if (withDeg && lane == 0) atomicAdd(&g_deg[dst], 1.0f);
    }
}

// ---------------------------------------------------------------------------
// GEMM1: h[n,c] = L2norm_row( [agg_mean(n)|x(n)] @ wT1 + b1l ), c in [0,128)
// 128 threads, 64-node x 128-ch tile; per-thread 4 nodes x 16 channels.
// ---------------------------------------------------------------------------
__global__ void __launch_bounds__(128) sage_gemm1(
    const float* __restrict__ xin, const float* __restrict__ bias, int Nn)
{
    __shared__ float wS[KC * 128];      // 16 KB
    __shared__ float inS[64 * ASTR];    // 9.2 KB
    __shared__ float rdegS[64];

    const int tid = threadIdx.x;
    const int ng = tid >> 3, cg = tid & 7;

    float4 b4[4];
#pragma unroll
    for (int m = 0; m < 4; m++) b4[m] = *(const float4*)&bias[m * 32 + cg * 4];

    for (int base = blockIdx.x * 64; base < Nn; base += gridDim.x * 64) {
        int nrem = min(64, Nn - base);
        if (tid < 64) {
            float d = (tid < nrem) ? g_deg[base + tid] : 1.f;
            rdegS[tid] = 1.f / fmaxf(d, 1.f);
        }

        float4 acc[4][4];
#pragma unroll
        for (int i = 0; i < 4; i++)
#pragma unroll
            for (int m = 0; m < 4; m++) acc[i][m] = make_float4(0.f, 0.f, 0.f, 0.f);

        for (int kc = 0; kc < 8; kc++) {
            __syncthreads();
            {
                const float4* wsrc = (const float4*)(g_wT1 + kc * KC * 128);
                float4* wdst = (float4*)wS;
                for (int i4 = tid; i4 < KC * 32; i4 += 128) wdst[i4] = wsrc[i4];
            }
            for (int i4 = tid; i4 < 64 * (KC / 4); i4 += 128) {
                int n = i4 >> 3;
                int kq = (i4 & 7) << 2;
                int k = kc * KC + kq;
                float4 v = make_float4(0.f, 0.f, 0.f, 0.f);
                if (n < nrem) {
                    if (k < 128) {
                        v = *(const float4*)&g_agg[(size_t)(base + n) * 128 + k];
                        float r = rdegS[n];
                        v.x *= r; v.y *= r; v.z *= r; v.w *= r;
                    } else {
                        v = *(const float4*)&xin[(size_t)(base + n) * 128 + (k - 128)];
                    }
                }
                *(float4*)&inS[n * ASTR + kq] = v;
            }
            __syncthreads();

#pragma unroll 4
            for (int kk = 0; kk < KC; kk++) {
                float4 w0 = *(const float4*)&wS[kk * 128 +  0 + (cg << 2)];
                float4 w1 = *(const float4*)&wS[kk * 128 + 32 + (cg << 2)];
                float4 w2 = *(const float4*)&wS[kk * 128 + 64 + (cg << 2)];
                float4 w3 = *(const float4*)&wS[kk * 128 + 96 + (cg << 2)];
#pragma unroll
                for (int i = 0; i < 4; i++) {
                    float a = inS[(ng * 4 + i) * ASTR + kk];
                    acc[i][0].x = fmaf(a, w0.x, acc[i][0].x);
                    acc[i][0].y = fmaf(a, w0.y, acc[i][0].y);
                    acc[i][0].z = fmaf(a, w0.z, acc[i][0].z);
                    acc[i][0].w = fmaf(a, w0.w, acc[i][0].w);
                    acc[i][1].x = fmaf(a, w1.x, acc[i][1].x);
                    acc[i][1].y = fmaf(a, w1.y, acc[i][1].y);
                    acc[i][1].z = fmaf(a, w1.z, acc[i][1].z);
                    acc[i][1].w = fmaf(a, w1.w, acc[i][1].w);
                    acc[i][2].x = fmaf(a, w2.x, acc[i][2].x);
                    acc[i][2].y = fmaf(a, w2.y, acc[i][2].y);
                    acc[i][2].z = fmaf(a, w2.z, acc[i][2].z);
                    acc[i][2].w = fmaf(a, w2.w, acc[i][2].w);
                    acc[i][3].x = fmaf(a, w3.x, acc[i][3].x);
                    acc[i][3].y = fmaf(a, w3.y, acc[i][3].y);
                    acc[i][3].z = fmaf(a, w3.z, acc[i][3].z);
                    acc[i][3].w = fmaf(a, w3.w, acc[i][3].w);
                }
            }
        }

#pragma unroll
        for (int i = 0; i < 4; i++) {
#pragma unroll
            for (int m = 0; m < 4; m++) {
                acc[i][m].x += b4[m].x; acc[i][m].y += b4[m].y;
                acc[i][m].z += b4[m].z; acc[i][m].w += b4[m].w;
            }
            float ss = 0.f;
#pragma unroll
            for (int m = 0; m < 4; m++)
                ss += acc[i][m].x * acc[i][m].x + acc[i][m].y * acc[i][m].y
                    + acc[i][m].z * acc[i][m].z + acc[i][m].w * acc[i][m].w;
            ss += __shfl_xor_sync(0xffffffffu, ss, 1);
            ss += __shfl_xor_sync(0xffffffffu, ss, 2);
            ss += __shfl_xor_sync(0xffffffffu, ss, 4);
            float inv = 1.f / fmaxf(sqrtf(ss), 1e-12f);
            int nl = ng * 4 + i;
            if (nl < nrem) {
                size_t n = (size_t)(base + nl);
#pragma unroll
                for (int m = 0; m < 4; m++) {
                    float4 r;
                    r.x = acc[i][m].x * inv; r.y = acc[i][m].y * inv;
                    r.z = acc[i][m].z * inv; r.w = acc[i][m].w * inv;
                    *(float4*)&g_h[n * 128 + m * 32 + cg * 4] = r;
                }
            }
        }
        __syncthreads();
    }
}

__global__ void __launch_bounds__(128) bn_reduce(int Nn) {
    int c = threadIdx.x;
    float s = 0.f, s2 = 0.f;
    for (int row = blockIdx.x; row < Nn; row += gridDim.x) {
        float v = g_h[(size_t)row * 128 + c];
        s += v; s2 += v * v;
    }
    atomicAdd(&g_bnsum[c], s);
    atomicAdd(&g_bnsq[c], s2);
}

__global__ void bn_finalize(const float* __restrict__ gamma, const float* __restrict__ beta, float invN) {
    int c = threadIdx.x;
    float mean = g_bnsum[c] * invN;
    float var = g_bnsq[c] * invN - mean * mean;
    float sc = gamma[c] * rsqrtf(var + 1e-5f);
    g_bnscale[c] = sc;
    g_bnshift[c] = beta[c] - mean * sc;
}

__global__ void bn_apply(int nf4) {
    int i = blockIdx.x * blockDim.x + threadIdx.x;
    int stride = gridDim.x * blockDim.x;
    float4* h4 = (float4*)g_h;
    const float4* sc4 = (const float4*)g_bnscale;
    const float4* sh4 = (const float4*)g_bnshift;
    for (int j = i; j < nf4; j += stride) {
        int c4 = j & 31;
        float4 v = h4[j], sc = sc4[c4], sh = sh4[c4];
        v.x = fmaxf(fmaf(v.x, sc.x, sh.x), 0.f);
        v.y = fmaxf(fmaf(v.y, sc.y, sh.y), 0.f);
        v.z = fmaxf(fmaf(v.z, sc.z, sh.z), 0.f);
        v.w = fmaxf(fmaf(v.w, sc.w, sh.w), 0.f);
        h4[j] = v;
    }
}

// ---------------------------------------------------------------------------
// GEMM2: out[n,c<47] = L2norm_row( [agg2_mean(n)|h(n)] @ wT2 + b2l )
// ---------------------------------------------------------------------------
__global__ void __launch_bounds__(128) sage_gemm2(
    const float* __restrict__ b2l, float* __restrict__ outp, int Nn)
{
    __shared__ float wS[KC * 48];       // 6 KB
    __shared__ float inS[64 * ASTR];    // 9.2 KB
    __shared__ float rdegS[64];

    const int tid = threadIdx.x;
    const int ng = tid >> 3, cg = tid & 7;

    float2 b2[3];
#pragma unroll
    for (int m = 0; m < 3; m++) {
        int c = m * 16 + cg * 2;
        b2[m].x = (c < 47) ? b2l[c] : 0.f;
        b2[m].y = (c + 1 < 47) ? b2l[c + 1] : 0.f;
    }

    for (int base = blockIdx.x * 64; base < Nn; base += gridDim.x * 64) {
        int nrem = min(64, Nn - base);
        if (tid < 64) {
            float d = (tid < nrem) ? g_deg[base + tid] : 1.f;
            rdegS[tid] = 1.f / fmaxf(d, 1.f);
        }

        float2 acc[4][3];
#pragma unroll
        for (int i = 0; i < 4; i++)
#pragma unroll
            for (int m = 0; m < 3; m++) acc[i][m] = make_float2(0.f, 0.f);

        for (int kc = 0; kc < 8; kc++) {
            __syncthreads();
            {
                const float4* wsrc = (const float4*)(g_wT2 + kc * KC * 48);
                float4* wdst = (float4*)wS;
                for (int i4 = tid; i4 < KC * 12; i4 += 128) wdst[i4] = wsrc[i4];
            }
            for (int i4 = tid; i4 < 64 * (KC / 4); i4 += 128) {
                int n = i4 >> 3;
                int kq = (i4 & 7) << 2;
                int k = kc * KC + kq;
                float4 v = make_float4(0.f, 0.f, 0.f, 0.f);
                if (n < nrem) {
                    if (k < 128) {
                        v = *(const float4*)&g_agg[(size_t)(base + n) * 128 + k];
                        float r = rdegS[n];
                        v.x *= r; v.y *= r; v.z *= r; v.w *= r;
                    } else {
                        v = *(const float4*)&g_h[(size_t)(base + n) * 128 + (k - 128)];
                    }
                }
                *(float4*)&inS[n * ASTR + kq] = v;
            }
            __syncthreads();

#pragma unroll 4
            for (int kk = 0; kk < KC; kk++) {
                float2 w0 = *(const float2*)&wS[kk * 48 +  0 + cg * 2];
                float2 w1 = *(const float2*)&wS[kk * 48 + 16 + cg * 2];
                float2 w2 = *(const float2*)&wS[kk * 48 + 32 + cg * 2];
#pragma unroll
                for (int i = 0; i < 4; i++) {
                    float a = inS[(ng * 4 + i) * ASTR + kk];
                    acc[i][0].x = fmaf(a, w0.x, acc[i][0].x);
                    acc[i][0].y = fmaf(a, w0.y, acc[i][0].y);
                    acc[i][1].x = fmaf(a, w1.x, acc[i][1].x);
                    acc[i][1].y = fmaf(a, w1.y, acc[i][1].y);
                    acc[i][2].x = fmaf(a, w2.x, acc[i][2].x);
                    acc[i][2].y = fmaf(a, w2.y, acc[i][2].y);
                }
            }
        }

#pragma unroll
        for (int i = 0; i < 4; i++) {
#pragma unroll
            for (int m = 0; m < 3; m++) { acc[i][m].x += b2[m].x; acc[i][m].y += b2[m].y; }
            float ss = 0.f;
#pragma unroll
            for (int m = 0; m < 3; m++)
                ss += acc[i][m].x * acc[i][m].x + acc[i][m].y * acc[i][m].y;
            ss += __shfl_xor_sync(0xffffffffu, ss, 1);
            ss += __shfl_xor_sync(0xffffffffu, ss, 2);
            ss += __shfl_xor_sync(0xffffffffu, ss, 4);
            float inv = 1.f / fmaxf(sqrtf(ss), 1e-12f);
            int nl = ng * 4 + i;
            if (nl < nrem) {
                size_t n = (size_t)(base + nl);
#pragma unroll
                for (int m = 0; m < 3; m++) {
                    int c0 = m * 16 + cg * 2;
                    outp[n * 47 + c0] = acc[i][m].x * inv;
                    if (c0 + 1 < 47) outp[n * 47 + c0 + 1] = acc[i][m].y * inv;
                }
            }
        }
        __syncthreads();
    }
}

// ---------------------------------------------------------------------------
extern "C" void kernel_launch(void* const* d_in, const int* in_sizes, int n_in,
                              void* d_out, int out_size) {
    const float* x     = (const float*)d_in[0];
    const void*  ei    = d_in[1];
    const float* w1l   = (const float*)d_in[2];
    const float* b1l   = (const float*)d_in[3];
    const float* w1r   = (const float*)d_in[4];
    const float* gamma = (const float*)d_in[5];
    const float* beta  = (const float*)d_in[6];
    const float* w2l   = (const float*)d_in[7];
    const float* b2l   = (const float*)d_in[8];
    const float* w2r   = (const float*)d_in[9];
    int Nn = in_sizes[0] / 128;
    int E  = in_sizes[1] / 2;

    int gb = (Nn + 63) / 64;

    detect_ei<<<1, 32>>>(ei, Nn);
    zero_kernel<<<2048, 256>>>(Nn * 32, 1, Nn);
    prep_weights<<<(256 * 128 + 255) / 256, 256>>>(w1l, w1r, w2l, w2r);
    scatter_kernel<<<2048, 256>>>(x, ei, E, 0, 1, Nn);
    sage_gemm1<<<gb, 128>>>(x, b1l, Nn);
    bn_reduce<<<512, 128>>>(Nn);
    bn_finalize<<<1, 128>>>(gamma, beta, 1.0f / (float)Nn);
    bn_apply<<<1024, 256>>>(Nn * 32);
    zero_kernel<<<2048, 256>>>(Nn * 32, 0, Nn);
    scatter_kernel<<<2048, 256>>>(nullptr, ei, E, 1, 0, Nn);
    sage_gemm2<<<gb, 128>>>(b2l, (float*)d_out, Nn);
}

// round 5
// speedup vs baseline: 1.1376x; 1.1376x over previous
#include <cuda_runtime.h>
#include <cstdint>
#include <cstddef>

// ---------------------------------------------------------------------------
// GraphSAGE 2-layer (N=100000, E=800000, 128 -> 128 -> 47, fp32):
//   scatter-mean -> GEMM1(+bias,+L2norm,+BN-stats, f32x2 packed FMA)
//   -> BN finalize -> BN+ReLU -> scatter-mean -> GEMM2(+bias,+L2norm) -> out
// edge_index dtype (int32 vs int64) detected on-device.
// ---------------------------------------------------------------------------

#define NMAX 100000
#define CH   128
#define KC   32          // K-chunk for GEMMs
#define ASTR 36          // inS row stride (KC + 4 pad)

typedef unsigned long long u64;

__device__ __align__(16) float g_agg[(size_t)NMAX * CH];
__device__ __align__(16) float g_h[(size_t)NMAX * CH];
__device__ __align__(16) float g_deg[NMAX];
__device__ __align__(16) float g_wT1[256 * 128];   // [k][c]
__device__ __align__(16) float g_wT2[256 * 48];    // [k][c] (c padded to 48)
__device__ __align__(16) float g_bnsum[128];
__device__ __align__(16) float g_bnsq[128];
__device__ __align__(16) float g_bnscale[128];
__device__ __align__(16) float g_bnshift[128];
__device__ int g_ei32;   // 1 if edge_index is int32, 0 if int64

// ---- f32x2 packed helpers (Blackwell FFMA2: only reachable via PTX) -------
__device__ __forceinline__ void ffma2(u64& acc, u64 a, u64 b) {
    asm("fma.rn.f32x2 %0, %1, %2, %0;" : "+l"(acc) : "l"(a), "l"(b));
}
__device__ __forceinline__ u64 pack2(float x, float y) {
    u64 r;
    asm("mov.b64 %0, {%1, %2};" : "=l"(r) : "f"(x), "f"(y));
    return r;
}
__device__ __forceinline__ float2 unpack2(u64 v) {
    float2 r;
    asm("mov.b64 {%0, %1}, %2;" : "=f"(r.x), "=f"(r.y) : "l"(v));
    return r;
}

// ---------------------------------------------------------------------------
__global__ void detect_ei(const void* ei, int Nn) {
    if (threadIdx.x == 0 && blockIdx.x == 0) {
        const long long* p = (const long long*)ei;
        int is32 = 0;
        for (int i = 0; i < 16; i++) {
            long long v = p[i];
            if (v < 0 || v >= (long long)Nn) { is32 = 1; break; }
        }
        g_ei32 = is32;
    }
}

__global__ void zero_kernel(int nf4, int withAux, int Nn) {
    int i = blockIdx.x * blockDim.x + threadIdx.x;
    int stride = gridDim.x * blockDim.x;
    float4 z = make_float4(0.f, 0.f, 0.f, 0.f);
    float4* a4 = (float4*)g_agg;
    for (int j = i; j < nf4; j += stride) a4[j] = z;
    if (withAux) {
        for (int j = i; j < Nn; j += stride) g_deg[j] = 0.f;
        if (i < 128) { g_bnsum[i] = 0.f; g_bnsq[i] = 0.f; }
    }
}

__global__ void prep_weights(const float* __restrict__ w1l, const float* __restrict__ w1r,
                             const float* __restrict__ w2l, const float* __restrict__ w2r) {
    int t = blockIdx.x * blockDim.x + threadIdx.x;
    if (t < 256 * 128) {
        int k = t >> 7, c = t & 127;
        g_wT1[t] = (k < 128) ? w1l[c * 128 + k] : w1r[c * 128 + (k - 128)];
    }
    if (t < 256 * 48) {
        int k = t / 48, c = t - k * 48;
        float v = 0.f;
        if (c < 47) v = (k < 128) ? w2l[c * 128 + k] : w2r[c * 128 + (k - 128)];
        g_wT2[t] = v;
    }
}

// One warp per edge: lane l covers columns {l, l+32, l+64, l+96}.
__global__ void __launch_bounds__(256) scatter_kernel(
    const float* __restrict__ feat, const void* __restrict__ ei,
    int E, int useH, int withDeg, int Nn)
{
    if (useH) feat = (const float*)g_h;
    const int is32 = g_ei32;
    int gw   = (blockIdx.x * blockDim.x + threadIdx.x) >> 5;
    int lane = threadIdx.x & 31;
    int nw   = (gridDim.x * blockDim.x) >> 5;
    for (int e = gw; e < E; e += nw) {
        int idx = -1;
        if (lane < 2) {
            size_t off = lane ? (size_t)E + e : (size_t)e;
            if (is32) idx = ((const int*)ei)[off];
            else      idx = (int)((const long long*)ei)[off];
        }
        int src = __shfl_sync(0xffffffffu, idx, 0);
        int dst = __shfl_sync(0xffffffffu, idx, 1);
        if ((unsigned)src >= (unsigned)Nn || (unsigned)dst >= (unsigned)Nn) continue;
        const float* sp = feat + (size_t)src * 128 + lane;
        float* dp = g_agg + (size_t)dst * 128 + lane;
        float v0 = sp[0];
        float v1 = sp[32];
        float v2 = sp[64];
        float v3 = sp[96];
        atomicAdd(dp +  0, v0);
        atomicAdd(dp + 32, v1);
        atomicAdd(dp + 64, v2);
        atomicAdd(dp + 96, v3);
        if (withDeg && lane == 0) atomicAdd(&g_deg[dst], 1.0f);
    }
}

// ---------------------------------------------------------------------------
// GEMM1: h[n,c] = L2norm_row( [agg_mean(n)|x(n)] @ wT1 + b1l ), c in [0,128)
// 128 threads, 64-node x 128-ch tile; per-thread 4 nodes x 16 channels,
// held as 8 f32x2 pairs; FFMA2 mainloop. Also accumulates BN sum/sumsq.
// Channel pairs: p -> c = (p>>1)*32 + cg*4 + (p&1)*2.
// ---------------------------------------------------------------------------
__global__ void __launch_bounds__(128) sage_gemm1(
    const float* __restrict__ xin, const float* __restrict__ bias, int Nn)
{
    __shared__ float wS[KC * 128];        // 16 KB
    __shared__ float inS[64 * ASTR];      // 9.2 KB
    __shared__ float rdegS[64];
    __shared__ float bnstage[2][4][128];  // 4 KB

    const int tid = threadIdx.x;
    const int ng = tid >> 3, cg = tid & 7;

    // bias pairs per channel pair
    float2 bp[8];
#pragma unroll
    for (int p = 0; p < 8; p++) {
        int c = (p >> 1) * 32 + cg * 4 + (p & 1) * 2;
        bp[p] = *(const float2*)&bias[c];
    }

    float2 s1[8], s2[8];
#pragma unroll
    for (int p = 0; p < 8; p++) { s1[p] = make_float2(0.f, 0.f); s2[p] = make_float2(0.f, 0.f); }

    for (int base = blockIdx.x * 64; base < Nn; base += gridDim.x * 64) {
        int nrem = min(64, Nn - base);
        if (tid < 64) {
            float d = (tid < nrem) ? g_deg[base + tid] : 1.f;
            rdegS[tid] = 1.f / fmaxf(d, 1.f);
        }

        u64 acc[4][8];
#pragma unroll
        for (int i = 0; i < 4; i++)
#pragma unroll
            for (int p = 0; p < 8; p++) acc[i][p] = 0ull;

        for (int kc = 0; kc < 8; kc++) {
            __syncthreads();
            {
                const float4* wsrc = (const float4*)(g_wT1 + kc * KC * 128);
                float4* wdst = (float4*)wS;
                for (int i4 = tid; i4 < KC * 32; i4 += 128) wdst[i4] = wsrc[i4];
            }
            for (int i4 = tid; i4 < 64 * (KC / 4); i4 += 128) {
                int n = i4 >> 3;
                int kq = (i4 & 7) << 2;
                int k = kc * KC + kq;
                float4 v = make_float4(0.f, 0.f, 0.f, 0.f);
                if (n < nrem) {
                    if (k < 128) {
                        v = *(const float4*)&g_agg[(size_t)(base + n) * 128 + k];
                        float r = rdegS[n];
                        v.x *= r; v.y *= r; v.z *= r; v.w *= r;
                    } else {
                        v = *(const float4*)&xin[(size_t)(base + n) * 128 + (k - 128)];
                    }
                }
                *(float4*)&inS[n * ASTR + kq] = v;
            }
            __syncthreads();

#pragma unroll 4
            for (int kk = 0; kk < KC; kk++) {
                const ulonglong2* wrow = (const ulonglong2*)&wS[kk * 128];
                ulonglong2 w0 = wrow[cg];
                ulonglong2 w1 = wrow[cg + 8];
                ulonglong2 w2 = wrow[cg + 16];
                ulonglong2 w3 = wrow[cg + 24];
#pragma unroll
                for (int i = 0; i < 4; i++) {
                    float a = inS[(ng * 4 + i) * ASTR + kk];
                    u64 aa = pack2(a, a);
                    ffma2(acc[i][0], aa, w0.x);
                    ffma2(acc[i][1], aa, w0.y);
                    ffma2(acc[i][2], aa, w1.x);
                    ffma2(acc[i][3], aa, w1.y);
                    ffma2(acc[i][4], aa, w2.x);
                    ffma2(acc[i][5], aa, w2.y);
                    ffma2(acc[i][6], aa, w3.x);
                    ffma2(acc[i][7], aa, w3.y);
                }
            }
        }

        // Epilogue: bias, row L2 norm, store h, BN partials
#pragma unroll
        for (int i = 0; i < 4; i++) {
            float2 v[8];
            float ss = 0.f;
#pragma unroll
            for (int p = 0; p < 8; p++) {
                v[p] = unpack2(acc[i][p]);
                v[p].x += bp[p].x; v[p].y += bp[p].y;
                ss += v[p].x * v[p].x + v[p].y * v[p].y;
            }
            ss += __shfl_xor_sync(0xffffffffu, ss, 1);
            ss += __shfl_xor_sync(0xffffffffu, ss, 2);
            ss += __shfl_xor_sync(0xffffffffu, ss, 4);
            float inv = 1.f / fmaxf(sqrtf(ss), 1e-12f);
            int nl = ng * 4 + i;
            if (nl < nrem) {
                size_t n = (size_t)(base + nl);
#pragma unroll
                for (int m = 0; m < 4; m++) {
                    float2 r0 = v[2 * m], r1 = v[2 * m + 1];
                    float4 r;
                    r.x = r0.x * inv; r.y = r0.y * inv;
                    r.z = r1.x * inv; r.w = r1.y * inv;
                    *(float4*)&g_h[n * 128 + m * 32 + cg * 4] = r;
                    s1[2 * m].x += r.x;     s1[2 * m].y += r.y;
                    s1[2 * m + 1].x += r.z; s1[2 * m + 1].y += r.w;
                    s2[2 * m].x += r.x * r.x;     s2[2 * m].y += r.y * r.y;
                    s2[2 * m + 1].x += r.z * r.z; s2[2 * m + 1].y += r.w * r.w;
                }
            }
        }
        __syncthreads();
    }

    // BN partial reduction: shuffle over ng within warp, stage to smem, sum, 1 global atomic/channel.
#pragma unroll
    for (int off = 8; off < 32; off <<= 1) {
#pragma unroll
        for (int p = 0; p < 8; p++) {
            s1[p].x += __shfl_xor_sync(0xffffffffu, s1[p].x, off);
            s1[p].y += __shfl_xor_sync(0xffffffffu, s1[p].y, off);
            s2[p].x += __shfl_xor_sync(0xffffffffu, s2[p].x, off);
            s2[p].y += __shfl_xor_sync(0xffffffffu, s2[p].y, off);
        }
    }
    int warp = tid >> 5, lane = tid & 31;
    if (lane < 8) {
#pragma unroll
        for (int p = 0; p < 8; p++) {
            int c = (p >> 1) * 32 + lane * 4 + (p & 1) * 2;
            bnstage[0][warp][c] = s1[p].x; bnstage[0][warp][c + 1] = s1[p].y;
            bnstage[1][warp][c] = s2[p].x; bnstage[1][warp][c + 1] = s2[p].y;
        }
    }
    __syncthreads();
    if (tid < 128) {
        float a0 = bnstage[0][0][tid] + bnstage[0][1][tid] + bnstage[0][2][tid] + bnstage[0][3][tid];
        float a1 = bnstage[1][0][tid] + bnstage[1][1][tid] + bnstage[1][2][tid] + bnstage[1][3][tid];
        atomicAdd(&g_bnsum[tid], a0);
        atomicAdd(&g_bnsq[tid], a1);
    }
}

__global__ void bn_finalize(const float* __restrict__ gamma, const float* __restrict__ beta, float invN) {
    int c = threadIdx.x;
    float mean = g_bnsum[c] * invN;
    float var = g_bnsq[c] * invN - mean * mean;
    float sc = gamma[c] * rsqrtf(var + 1e-5f);
    g_bnscale[c] = sc;
    g_bnshift[c] = beta[c] - mean * sc;
}

__global__ void bn_apply(int nf4) {
    int i = blockIdx.x * blockDim.x + threadIdx.x;
    int stride = gridDim.x * blockDim.x;
    float4* h4 = (float4*)g_h;
    const float4* sc4 = (const float4*)g_bnscale;
    const float4* sh4 = (const float4*)g_bnshift;
    for (int j = i; j < nf4; j += stride) {
        int c4 = j & 31;
        float4 v = h4[j], sc = sc4[c4], sh = sh4[c4];
        v.x = fmaxf(fmaf(v.x, sc.x, sh.x), 0.f);
        v.y = fmaxf(fmaf(v.y, sc.y, sh.y), 0.f);
        v.z = fmaxf(fmaf(v.z, sc.z, sh.z), 0.f);
        v.w = fmaxf(fmaf(v.w, sc.w, sh.w), 0.f);
        h4[j] = v;
    }
}

// ---------------------------------------------------------------------------
// GEMM2: out[n,c<47] = L2norm_row( [agg2_mean(n)|h(n)] @ wT2 + b2l )
// Per-thread 4 nodes x 3 channel pairs (FFMA2); c = m*16 + cg*2.
// ---------------------------------------------------------------------------
__global__ void __launch_bounds__(128) sage_gemm2(
    const float* __restrict__ b2l, float* __restrict__ outp, int Nn)
{
    __shared__ float wS[KC * 48];       // 6 KB
    __shared__ float inS[64 * ASTR];    // 9.2 KB
    __shared__ float rdegS[64];

    const int tid = threadIdx.x;
    const int ng = tid >> 3, cg = tid & 7;

    float2 b2[3];
#pragma unroll
    for (int m = 0; m < 3; m++) {
        int c = m * 16 + cg * 2;
        b2[m].x = (c < 47) ? b2l[c] : 0.f;
        b2[m].y = (c + 1 < 47) ? b2l[c + 1] : 0.f;
    }

    for (int base = blockIdx.x * 64; base < Nn; base += gridDim.x * 64) {
        int nrem = min(64, Nn - base);
        if (tid < 64) {
            float d = (tid < nrem) ? g_deg[base + tid] : 1.f;
            rdegS[tid] = 1.f / fmaxf(d, 1.f);
        }

        u64 acc[4][3];
#pragma unroll
        for (int i = 0; i < 4; i++)
#pragma unroll
            for (int m = 0; m < 3; m++) acc[i][m] = 0ull;

        for (int kc = 0; kc < 8; kc++) {
            __syncthreads();
            {
                const float4* wsrc = (const float4*)(g_wT2 + kc * KC * 48);
                float4* wdst = (float4*)wS;
                for (int i4 = tid; i4 < KC * 12; i4 += 128) wdst[i4] = wsrc[i4];
            }
            for (int i4 = tid; i4 < 64 * (KC / 4); i4 += 128) {
                int n = i4 >> 3;
                int kq = (i4 & 7) << 2;
                int k = kc * KC + kq;
                float4 v = make_float4(0.f, 0.f, 0.f, 0.f);
                if (n < nrem) {
                    if (k < 128) {
                        v = *(const float4*)&g_agg[(size_t)(base + n) * 128 + k];
                        float r = rdegS[n];
                        v.x *= r; v.y *= r; v.z *= r; v.w *= r;
                    } else {
                        v = *(const float4*)&g_h[(size_t)(base + n) * 128 + (k - 128)];
                    }
                }
                *(float4*)&inS[n * ASTR + kq] = v;
            }
            __syncthreads();

#pragma unroll 4
            for (int kk = 0; kk < KC; kk++) {
                u64 w0 = *(const u64*)&wS[kk * 48 +  0 + cg * 2];
                u64 w1 = *(const u64*)&wS[kk * 48 + 16 + cg * 2];
                u64 w2 = *(const u64*)&wS[kk * 48 + 32 + cg * 2];
#pragma unroll
                for (int i = 0; i < 4; i++) {
                    float a = inS[(ng * 4 + i) * ASTR + kk];
                    u64 aa = pack2(a, a);
                    ffma2(acc[i][0], aa, w0);
                    ffma2(acc[i][1], aa, w1);
                    ffma2(acc[i][2], aa, w2);
                }
            }
        }

#pragma unroll
        for (int i = 0; i < 4; i++) {
            float2 v[3];
            float ss = 0.f;
#pragma unroll
            for (int m = 0; m < 3; m++) {
                v[m] = unpack2(acc[i][m]);
                v[m].x += b2[m].x; v[m].y += b2[m].y;
                ss += v[m].x * v[m].x + v[m].y * v[m].y;
            }
            ss += __shfl_xor_sync(0xffffffffu, ss, 1);
            ss += __shfl_xor_sync(0xffffffffu, ss, 2);
            ss += __shfl_xor_sync(0xffffffffu, ss, 4);
            float inv = 1.f / fmaxf(sqrtf(ss), 1e-12f);
            int nl = ng * 4 + i;
            if (nl < nrem) {
                size_t n = (size_t)(base + nl);
#pragma unroll
                for (int m = 0; m < 3; m++) {
                    int c0 = m * 16 + cg * 2;
                    outp[n * 47 + c0] = v[m].x * inv;
                    if (c0 + 1 < 47) outp[n * 47 + c0 + 1] = v[m].y * inv;
                }
            }
        }
        __syncthreads();
    }
}

// ---------------------------------------------------------------------------
extern "C" void kernel_launch(void* const* d_in, const int* in_sizes, int n_in,
                              void* d_out, int out_size) {
    const float* x     = (const float*)d_in[0];
    const void*  ei    = d_in[1];
    const float* w1l   = (const float*)d_in[2];
    const float* b1l   = (const float*)d_in[3];
    const float* w1r   = (const float*)d_in[4];
    const float* gamma = (const float*)d_in[5];
    const float* beta  = (const float*)d_in[6];
    const float* w2l   = (const float*)d_in[7];
    const float* b2l   = (const float*)d_in[8];
    const float* w2r   = (const float*)d_in[9];
    int Nn = in_sizes[0] / 128;
    int E  = in_sizes[1] / 2;

    int gb = (Nn + 63) / 64;

    detect_ei<<<1, 32>>>(ei, Nn);
    zero_kernel<<<2048, 256>>>(Nn * 32, 1, Nn);
    prep_weights<<<(256 * 128 + 255) / 256, 256>>>(w1l, w1r, w2l, w2r);
    scatter_kernel<<<2048, 256>>>(x, ei, E, 0, 1, Nn);
    sage_gemm1<<<gb, 128>>>(x, b1l, Nn);
    bn_finalize<<<1, 128>>>(gamma, beta, 1.0f / (float)Nn);
    bn_apply<<<1024, 256>>>(Nn * 32);
    zero_kernel<<<2048, 256>>>(Nn * 32, 0, Nn);
    scatter_kernel<<<2048, 256>>>(nullptr, ei, E, 1, 0, Nn);
    sage_gemm2<<<gb, 128>>>(b2l, (float*)d_out, Nn);
}

// round 6
// speedup vs baseline: 1.4512x; 1.2757x over previous
#include <cuda_runtime.h>
#include <cstdint>
#include <cstddef>

// ---------------------------------------------------------------------------
// GraphSAGE 2-layer (N=100000, E=800000, 128 -> 128 -> 47, fp32):
//   adjacency build (bucketed slots) -> gather-mean -> GEMM1(+bias,+L2norm,
//   +BN stats, FFMA2) -> BN finalize -> BN+ReLU -> gather-mean -> GEMM2 -> out
// No scatter atomics on feature data; no accumulator zeroing passes.
// edge_index dtype (int32 vs int64) detected on-device.
// ---------------------------------------------------------------------------

#define NMAX 100000
#define CH   128
#define KC   32          // K-chunk for GEMMs
#define ASTR 36          // inS row stride (KC + 4 pad)
#define SLOTS 64         // max neighbors stored per node (P(overflow) ~ 0)

typedef unsigned long long u64;

__device__ __align__(16) float g_agg[(size_t)NMAX * CH];
__device__ __align__(16) float g_h[(size_t)NMAX * CH];
__device__ __align__(16) int   g_cnt[NMAX];
__device__ __align__(16) int   g_slot[(size_t)NMAX * SLOTS];
__device__ __align__(16) float g_wT1[256 * 128];   // [k][c]
__device__ __align__(16) float g_wT2[256 * 48];    // [k][c] (c padded to 48)
__device__ __align__(16) float g_bnsum[128];
__device__ __align__(16) float g_bnsq[128];
__device__ __align__(16) float g_bnscale[128];
__device__ __align__(16) float g_bnshift[128];
__device__ int g_ei32;   // 1 if edge_index is int32, 0 if int64

// ---- f32x2 packed helpers (Blackwell FFMA2: only reachable via PTX) -------
__device__ __forceinline__ void ffma2(u64& acc, u64 a, u64 b) {
    asm("fma.rn.f32x2 %0, %1, %2, %0;" : "+l"(acc) : "l"(a), "l"(b));
}
__device__ __forceinline__ u64 pack2(float x, float y) {
    u64 r;
    asm("mov.b64 %0, {%1, %2};" : "=l"(r) : "f"(x), "f"(y));
    return r;
}
__device__ __forceinline__ float2 unpack2(u64 v) {
    float2 r;
    asm("mov.b64 {%0, %1}, %2;" : "=f"(r.x), "=f"(r.y) : "l"(v));
    return r;
}

// ---------------------------------------------------------------------------
__global__ void detect_ei(const void* ei, int Nn) {
    if (threadIdx.x == 0 && blockIdx.x == 0) {
        const long long* p = (const long long*)ei;
        int is32 = 0;
        for (int i = 0; i < 16; i++) {
            long long v = p[i];
            if (v < 0 || v >= (long long)Nn) { is32 = 1; break; }
        }
        g_ei32 = is32;
    }
}

__global__ void zero_small(int Nn) {
    int i = blockIdx.x * blockDim.x + threadIdx.x;
    int stride = gridDim.x * blockDim.x;
    for (int j = i; j < Nn; j += stride) g_cnt[j] = 0;
    if (i < 128) { g_bnsum[i] = 0.f; g_bnsq[i] = 0.f; }
}

__global__ void prep_weights(const float* __restrict__ w1l, const float* __restrict__ w1r,
                             const float* __restrict__ w2l, const float* __restrict__ w2r) {
    int t = blockIdx.x * blockDim.x + threadIdx.x;
    if (t < 256 * 128) {
        int k = t >> 7, c = t & 127;
        g_wT1[t] = (k < 128) ? w1l[c * 128 + k] : w1r[c * 128 + (k - 128)];
    }
    if (t < 256 * 48) {
        int k = t / 48, c = t - k * 48;
        float v = 0.f;
        if (c < 47) v = (k < 128) ? w2l[c * 128 + k] : w2r[c * 128 + (k - 128)];
        g_wT2[t] = v;
    }
}

// Build bucketed adjacency: slot[dst*SLOTS + pos] = src.
__global__ void __launch_bounds__(256) build_adj(
    const void* __restrict__ ei, int E, int Nn)
{
    const int is32 = g_ei32;
    int t = blockIdx.x * blockDim.x + threadIdx.x;
    int stride = gridDim.x * blockDim.x;
    for (int e = t; e < E; e += stride) {
        int src, dst;
        if (is32) {
            src = ((const int*)ei)[e];
            dst = ((const int*)ei)[(size_t)E + e];
        } else {
            src = (int)((const long long*)ei)[e];
            dst = (int)((const long long*)ei)[(size_t)E + e];
        }
        if ((unsigned)src >= (unsigned)Nn || (unsigned)dst >= (unsigned)Nn) continue;
        int pos = atomicAdd(&g_cnt[dst], 1);
        if (pos < SLOTS) g_slot[(size_t)dst * SLOTS + pos] = src;
    }
}

// Gather-mean: one warp per node; lane l owns columns {l, l+32, l+64, l+96}.
// Reads are dense 128B waves; writes are dense 128B waves; no atomics.
__global__ void __launch_bounds__(256) gather_mean(
    const float* __restrict__ feat, int useH, int Nn)
{
    if (useH) feat = (const float*)g_h;
    int gw   = (blockIdx.x * blockDim.x + threadIdx.x) >> 5;
    int lane = threadIdx.x & 31;
    int nw   = (gridDim.x * blockDim.x) >> 5;
    for (int n = gw; n < Nn; n += nw) {
        int cnt = g_cnt[n];
        int m = min(cnt, SLOTS);
        const int* sl = g_slot + (size_t)n * SLOTS;
        float a0 = 0.f, a1 = 0.f, a2 = 0.f, a3 = 0.f;
        int j = 0;
        for (; j + 2 <= m; j += 2) {
            int s0 = sl[j], s1 = sl[j + 1];
            const float* p0 = feat + (size_t)s0 * 128 + lane;
            const float* p1 = feat + (size_t)s1 * 128 + lane;
            float x0 = p0[0], x1 = p0[32], x2 = p0[64], x3 = p0[96];
            float y0 = p1[0], y1 = p1[32], y2 = p1[64], y3 = p1[96];
            a0 += x0 + y0; a1 += x1 + y1; a2 += x2 + y2; a3 += x3 + y3;
        }
        if (j < m) {
            const float* p0 = feat + (size_t)sl[j] * 128 + lane;
            a0 += p0[0]; a1 += p0[32]; a2 += p0[64]; a3 += p0[96];
        }
        float r = 1.f / fmaxf((float)cnt, 1.f);
        float* dp = g_agg + (size_t)n * 128 + lane;
        dp[0]  = a0 * r;
        dp[32] = a1 * r;
        dp[64] = a2 * r;
        dp[96] = a3 * r;
    }
}

// ---------------------------------------------------------------------------
// GEMM1: h[n,c] = L2norm_row( [agg(n)|x(n)] @ wT1 + b1l ), c in [0,128)
// 128 threads, 64-node x 128-ch tile; per-thread 4 nodes x 16 channels,
// FFMA2 mainloop; fused BN sum/sumsq.
// ---------------------------------------------------------------------------
__global__ void __launch_bounds__(128) sage_gemm1(
    const float* __restrict__ xin, const float* __restrict__ bias, int Nn)
{
    __shared__ float wS[KC * 128];        // 16 KB
    __shared__ float inS[64 * ASTR];      // 9.2 KB
    __shared__ float bnstage[2][4][128];  // 4 KB

    const int tid = threadIdx.x;
    const int ng = tid >> 3, cg = tid & 7;

    float2 bp[8];
#pragma unroll
    for (int p = 0; p < 8; p++) {
        int c = (p >> 1) * 32 + cg * 4 + (p & 1) * 2;
        bp[p] = *(const float2*)&bias[c];
    }

    float2 s1[8], s2[8];
#pragma unroll
    for (int p = 0; p < 8; p++) { s1[p] = make_float2(0.f, 0.f); s2[p] = make_float2(0.f, 0.f); }

    for (int base = blockIdx.x * 64; base < Nn; base += gridDim.x * 64) {
        int nrem = min(64, Nn - base);

        u64 acc[4][8];
#pragma unroll
        for (int i = 0; i < 4; i++)
#pragma unroll
            for (int p = 0; p < 8; p++) acc[i][p] = 0ull;

        for (int kc = 0; kc < 8; kc++) {
            __syncthreads();
            {
                const float4* wsrc = (const float4*)(g_wT1 + kc * KC * 128);
                float4* wdst = (float4*)wS;
                for (int i4 = tid; i4 < KC * 32; i4 += 128) wdst[i4] = wsrc[i4];
            }
            for (int i4 = tid; i4 < 64 * (KC / 4); i4 += 128) {
                int n = i4 >> 3;
                int kq = (i4 & 7) << 2;
                int k = kc * KC + kq;
                float4 v = make_float4(0.f, 0.f, 0.f, 0.f);
                if (n < nrem) {
                    if (k < 128) v = *(const float4*)&g_agg[(size_t)(base + n) * 128 + k];
                    else         v = *(const float4*)&xin[(size_t)(base + n) * 128 + (k - 128)];
                }
                *(float4*)&inS[n * ASTR + kq] = v;
            }
            __syncthreads();

#pragma unroll 4
            for (int kk = 0; kk < KC; kk++) {
                const ulonglong2* wrow = (const ulonglong2*)&wS[kk * 128];
                ulonglong2 w0 = wrow[cg];
                ulonglong2 w1 = wrow[cg + 8];
                ulonglong2 w2 = wrow[cg + 16];
                ulonglong2 w3 = wrow[cg + 24];
#pragma unroll
                for (int i = 0; i < 4; i++) {
                    float a = inS[(ng * 4 + i) * ASTR + kk];
                    u64 aa = pack2(a, a);
                    ffma2(acc[i][0], aa, w0.x);
                    ffma2(acc[i][1], aa, w0.y);
                    ffma2(acc[i][2], aa, w1.x);
                    ffma2(acc[i][3], aa, w1.y);
                    ffma2(acc[i][4], aa, w2.x);
                    ffma2(acc[i][5], aa, w2.y);
                    ffma2(acc[i][6], aa, w3.x);
                    ffma2(acc[i][7], aa, w3.y);
                }
            }
        }

        // Epilogue: bias, row L2 norm, store h, BN partials
#pragma unroll
        for (int i = 0; i < 4; i++) {
            float2 v[8];
            float ss = 0.f;
#pragma unroll
            for (int p = 0; p < 8; p++) {
                v[p] = unpack2(acc[i][p]);
                v[p].x += bp[p].x; v[p].y += bp[p].y;
                ss += v[p].x * v[p].x + v[p].y * v[p].y;
            }
            ss += __shfl_xor_sync(0xffffffffu, ss, 1);
            ss += __shfl_xor_sync(0xffffffffu, ss, 2);
            ss += __shfl_xor_sync(0xffffffffu, ss, 4);
            float inv = 1.f / fmaxf(sqrtf(ss), 1e-12f);
            int nl = ng * 4 + i;
            if (nl < nrem) {
                size_t n = (size_t)(base + nl);
#pragma unroll
                for (int m = 0; m < 4; m++) {
                    float2 r0 = v[2 * m], r1 = v[2 * m + 1];
                    float4 r;
                    r.x = r0.x * inv; r.y = r0.y * inv;
                    r.z = r1.x * inv; r.w = r1.y * inv;
                    *(float4*)&g_h[n * 128 + m * 32 + cg * 4] = r;
                    s1[2 * m].x += r.x;     s1[2 * m].y += r.y;
                    s1[2 * m + 1].x += r.z; s1[2 * m + 1].y += r.w;
                    s2[2 * m].x += r.x * r.x;     s2[2 * m].y += r.y * r.y;
                    s2[2 * m + 1].x += r.z * r.z; s2[2 * m + 1].y += r.w * r.w;
                }
            }
        }
        __syncthreads();
    }

    // BN partial reduction: shuffle over node-groups, stage via smem, 1 global atomic/channel.
#pragma unroll
    for (int off = 8; off < 32; off <<= 1) {
#pragma unroll
        for (int p = 0; p < 8; p++) {
            s1[p].x += __shfl_xor_sync(0xffffffffu, s1[p].x, off);
            s1[p].y += __shfl_xor_sync(0xffffffffu, s1[p].y, off);
            s2[p].x += __shfl_xor_sync(0xffffffffu, s2[p].x, off);
            s2[p].y += __shfl_xor_sync(0xffffffffu, s2[p].y, off);
        }
    }
    int warp = tid >> 5, lane = tid & 31;
    if (lane < 8) {
#pragma unroll
        for (int p = 0; p < 8; p++) {
            int c = (p >> 1) * 32 + lane * 4 + (p & 1) * 2;
            bnstage[0][warp][c] = s1[p].x; bnstage[0][warp][c + 1] = s1[p].y;
            bnstage[1][warp][c] = s2[p].x; bnstage[1][warp][c + 1] = s2[p].y;
        }
    }
    __syncthreads();
    if (tid < 128) {
        float a0 = bnstage[0][0][tid] + bnstage[0][1][tid] + bnstage[0][2][tid] + bnstage[0][3][tid];
        float a1 = bnstage[1][0][tid] + bnstage[1][1][tid] + bnstage[1][2][tid] + bnstage[1][3][tid];
        atomicAdd(&g_bnsum[tid], a0);
        atomicAdd(&g_bnsq[tid], a1);
    }
}

__global__ void bn_finalize(const float* __restrict__ gamma, const float* __restrict__ beta, float invN) {
    int c = threadIdx.x;
    float mean = g_bnsum[c] * invN;
    float var = g_bnsq[c] * invN - mean * mean;
    float sc = gamma[c] * rsqrtf(var + 1e-5f);
    g_bnscale[c] = sc;
    g_bnshift[c] = beta[c] - mean * sc;
}

__global__ void bn_apply(int nf4) {
    int i = blockIdx.x * blockDim.x + threadIdx.x;
    int stride = gridDim.x * blockDim.x;
    float4* h4 = (float4*)g_h;
    const float4* sc4 = (const float4*)g_bnscale;
    const float4* sh4 = (const float4*)g_bnshift;
    for (int j = i; j < nf4; j += stride) {
        int c4 = j & 31;
        float4 v = h4[j], sc = sc4[c4], sh = sh4[c4];
        v.x = fmaxf(fmaf(v.x, sc.x, sh.x), 0.f);
        v.y = fmaxf(fmaf(v.y, sc.y, sh.y), 0.f);
        v.z = fmaxf(fmaf(v.z, sc.z, sh.z), 0.f);
        v.w = fmaxf(fmaf(v.w, sc.w, sh.w), 0.f);
        h4[j] = v;
    }
}

// ---------------------------------------------------------------------------
// GEMM2: out[n,c<47] = L2norm_row( [agg2(n)|h(n)] @ wT2 + b2l )
// ---------------------------------------------------------------------------
__global__ void __launch_bounds__(128) sage_gemm2(
    const float* __restrict__ b2l, float* __restrict__ outp, int Nn)
{
    __shared__ float wS[KC * 48];       // 6 KB
    __shared__ float inS[64 * ASTR];    // 9.2 KB

    const int tid = threadIdx.x;
    const int ng = tid >> 3, cg = tid & 7;

    float2 b2[3];
#pragma unroll
    for (int m = 0; m < 3; m++) {
        int c = m * 16 + cg * 2;
        b2[m].x = (c < 47) ? b2l[c] : 0.f;
        b2[m].y = (c + 1 < 47) ? b2l[c + 1] : 0.f;
    }

    for (int base = blockIdx.x * 64; base < Nn; base += gridDim.x * 64) {
        int nrem = min(64, Nn - base);

        u64 acc[4][3];
#pragma unroll
        for (int i = 0; i < 4; i++)
#pragma unroll
            for (int m = 0; m < 3; m++) acc[i][m] = 0ull;

        for (int kc = 0; kc < 8; kc++) {
            __syncthreads();
            {
                const float4* wsrc = (const float4*)(g_wT2 + kc * KC * 48);
                float4* wdst = (float4*)wS;
                for (int i4 = tid; i4 < KC * 12; i4 += 128) wdst[i4] = wsrc[i4];
            }
            for (int i4 = tid; i4 < 64 * (KC / 4); i4 += 128) {
                int n = i4 >> 3;
                int kq = (i4 & 7) << 2;
                int k = kc * KC + kq;
                float4 v = make_float4(0.f, 0.f, 0.f, 0.f);
                if (n < nrem) {
                    if (k < 128) v = *(const float4*)&g_agg[(size_t)(base + n) * 128 + k];
                    else         v = *(const float4*)&g_h[(size_t)(base + n) * 128 + (k - 128)];
                }
                *(float4*)&inS[n * ASTR + kq] = v;
            }
            __syncthreads();

#pragma unroll 4
            for (int kk = 0; kk < KC; kk++) {
                u64 w0 = *(const u64*)&wS[kk * 48 +  0 + cg * 2];
                u64 w1 = *(const u64*)&wS[kk * 48 + 16 + cg * 2];
                u64 w2 = *(const u64*)&wS[kk * 48 + 32 + cg * 2];
#pragma unroll
                for (int i = 0; i < 4; i++) {
                    float a = inS[(ng * 4 + i) * ASTR + kk];
                    u64 aa = pack2(a, a);
                    ffma2(acc[i][0], aa, w0);
                    ffma2(acc[i][1], aa, w1);
                    ffma2(acc[i][2], aa, w2);
                }
            }
        }

#pragma unroll
        for (int i = 0; i < 4; i++) {
            float2 v[3];
            float ss = 0.f;
#pragma unroll
            for (int m = 0; m < 3; m++) {
                v[m] = unpack2(acc[i][m]);
                v[m].x += b2[m].x; v[m].y += b2[m].y;
                ss += v[m].x * v[m].x + v[m].y * v[m].y;
            }
            ss += __shfl_xor_sync(0xffffffffu, ss, 1);
            ss += __shfl_xor_sync(0xffffffffu, ss, 2);
            ss += __shfl_xor_sync(0xffffffffu, ss, 4);
            float inv = 1.f / fmaxf(sqrtf(ss), 1e-12f);
            int nl = ng * 4 + i;
            if (nl < nrem) {
                size_t n = (size_t)(base + nl);
#pragma unroll
                for (int m = 0; m < 3; m++) {
                    int c0 = m * 16 + cg * 2;
                    outp[n * 47 + c0] = v[m].x * inv;
                    if (c0 + 1 < 47) outp[n * 47 + c0 + 1] = v[m].y * inv;
                }
            }
        }
        __syncthreads();
    }
}

// ---------------------------------------------------------------------------
extern "C" void kernel_launch(void* const* d_in, const int* in_sizes, int n_in,
                              void* d_out, int out_size) {
    const float* x     = (const float*)d_in[0];
    const void*  ei    = d_in[1];
    const float* w1l   = (const float*)d_in[2];
    const float* b1l   = (const float*)d_in[3];
    const float* w1r   = (const float*)d_in[4];
    const float* gamma = (const float*)d_in[5];
    const float* beta  = (const float*)d_in[6];
    const float* w2l   = (const float*)d_in[7];
    const float* b2l   = (const float*)d_in[8];
    const float* w2r   = (const float*)d_in[9];
    int Nn = in_sizes[0] / 128;
    int E  = in_sizes[1] / 2;

    int gb = (Nn + 63) / 64;

    detect_ei<<<1, 32>>>(ei, Nn);
    zero_small<<<256, 256>>>(Nn);
    prep_weights<<<(256 * 128 + 255) / 256, 256>>>(w1l, w1r, w2l, w2r);
    build_adj<<<(E + 255) / 256, 256>>>(ei, E, Nn);
    gather_mean<<<2048, 256>>>(x, 0, Nn);
    sage_gemm1<<<gb, 128>>>(x, b1l, Nn);
    bn_finalize<<<1, 128>>>(gamma, beta, 1.0f / (float)Nn);
    bn_apply<<<1024, 256>>>(Nn * 32);
    gather_mean<<<2048, 256>>>(nullptr, 1, Nn);
    sage_gemm2<<<gb, 128>>>(b2l, (float*)d_out, Nn);
}